// round 13
// baseline (speedup 1.0000x reference)
#include <cuda_runtime.h>
#include <cuda_fp16.h>
#include <cstdint>

// Problem constants
#define BB 2
#define SS 2048
#define DD 1024
#define HH 16
#define HDD 64
#define MROWS (BB * SS)          // 4096
static constexpr float QMULT = 1.4426950408889634f / 32.0f;  // log2(e)/sqrt(D)

// ---------------------------------------------------------------------------
// Device scratch
// ---------------------------------------------------------------------------
__device__ __half g_Qs[(size_t)BB * HH * SS * 64];   // [BH,S,64] (pre-scaled)
__device__ __half g_Ks[(size_t)BB * HH * SS * 64];
__device__ __half g_Vs[(size_t)BB * HH * SS * 64];
__device__ __half g_ctxh[(size_t)MROWS * DD];        // [B*S, D] fp16 ctx
__device__ __half g_W16[(size_t)4 * DD * DD];        // Wq|Wk|Wv|Wo fp16

// ---------------------------------------------------------------------------
// Helpers (baseline PTX only: cp.async / ldmatrix / mma.sync)
// ---------------------------------------------------------------------------
__device__ __forceinline__ uint32_t smem_u32(const void* p) {
    uint32_t a;
    asm("{ .reg .u64 t; cvta.to.shared.u64 t, %1; cvt.u32.u64 %0, t; }" : "=r"(a) : "l"(p));
    return a;
}
__device__ __forceinline__ void cp16(uint32_t s, const void* g) {
    asm volatile("cp.async.cg.shared.global [%0], [%1], 16;" :: "r"(s), "l"(g));
}
__device__ __forceinline__ void cp_commit() {
    asm volatile("cp.async.commit_group;" ::: "memory");
}
template <int N>
__device__ __forceinline__ void cp_wait() {
    asm volatile("cp.async.wait_group %0;" :: "n"(N) : "memory");
}
__device__ __forceinline__ void ldm_x4(uint32_t* r, uint32_t addr) {
    asm volatile("ldmatrix.sync.aligned.m8n8.x4.shared.b16 {%0,%1,%2,%3}, [%4];"
                 : "=r"(r[0]), "=r"(r[1]), "=r"(r[2]), "=r"(r[3]) : "r"(addr));
}
__device__ __forceinline__ void ldm_x4_t(uint32_t* r, uint32_t addr) {
    asm volatile("ldmatrix.sync.aligned.m8n8.x4.trans.shared.b16 {%0,%1,%2,%3}, [%4];"
                 : "=r"(r[0]), "=r"(r[1]), "=r"(r[2]), "=r"(r[3]) : "r"(addr));
}
__device__ __forceinline__ void mma16816(float* d, const uint32_t* a, const uint32_t* b) {
    asm volatile(
        "mma.sync.aligned.m16n8k16.row.col.f32.f16.f16.f32 "
        "{%0,%1,%2,%3}, {%4,%5,%6,%7}, {%8,%9}, {%0,%1,%2,%3};"
        : "+f"(d[0]), "+f"(d[1]), "+f"(d[2]), "+f"(d[3])
        : "r"(a[0]), "r"(a[1]), "r"(a[2]), "r"(a[3]), "r"(b[0]), "r"(b[1]));
}
__device__ __forceinline__ float ex2f(float x) {
    float r;
    asm("ex2.approx.ftz.f32 %0, %1;" : "=f"(r) : "f"(x));
    return r;
}
__device__ __forceinline__ uint32_t pack_h2(float x, float y) {
    __half2 h2; h2.x = __float2half_rn(x); h2.y = __float2half_rn(y);
    return *reinterpret_cast<uint32_t*>(&h2);
}

// ---------------------------------------------------------------------------
// Convert all 4 weight matrices fp32->fp16 in one launch.
// ---------------------------------------------------------------------------
__global__ __launch_bounds__(256) void conv_w(const float* __restrict__ w0,
                                              const float* __restrict__ w1,
                                              const float* __restrict__ w2,
                                              const float* __restrict__ w3,
                                              __half* __restrict__ out) {
    int idx = blockIdx.x * 256 + threadIdx.x;      // float4 units
    const int per = DD * DD / 4;                   // 262144
    int wsel = idx / per;
    int off = idx - wsel * per;
    const float* src = (wsel == 0) ? w0 : (wsel == 1) ? w1 : (wsel == 2) ? w2 : w3;
    float4 x = reinterpret_cast<const float4*>(src)[off];
    __half2 a; a.x = __float2half_rn(x.x); a.y = __float2half_rn(x.y);
    __half2 b; b.x = __float2half_rn(x.z); b.y = __float2half_rn(x.w);
    __half2* o = reinterpret_cast<__half2*>(out + (size_t)wsel * DD * DD) + off * 2;
    o[0] = a; o[1] = b;
}

// ---------------------------------------------------------------------------
// GEMM geometry: CTA tile 128(M) x 256(N), 512 threads = 16 warps (4m x 4n),
// warp tile 32x64. 6-stage smem ring, TWO 32-K chunks per barrier
// (16 barriers total), cp.async lookahead = 1 pair.
// ---------------------------------------------------------------------------
#define LDHW 40                  // smem row stride in halfwords (80 bytes)
#define LD2  (LDHW * 2)
#define A_STG ((uint32_t)(128 * LD2))    // 10240 B per A stage
#define B_STG ((uint32_t)(256 * LD2))    // 20480 B per B stage
#define NSTG 6
#define GEMM_SMEM (NSTG * (128 * LD2) + NSTG * (256 * LD2))   // 184320 B

// ---------------------------------------------------------------------------
// QKV GEMM (fused A-side fp32->fp16): grid (4, 32, 3), 512 threads.
// ---------------------------------------------------------------------------
__global__ __launch_bounds__(512, 1) void gemm_qkv(const float* __restrict__ Aq,
                                                   const float* __restrict__ Ak,
                                                   const float* __restrict__ Av,
                                                   const __half* __restrict__ W16,
                                                   __half* __restrict__ qs,
                                                   __half* __restrict__ ks,
                                                   __half* __restrict__ vs) {
    extern __shared__ __align__(16) __half dsm[];
    const uint32_t base = smem_u32(dsm);
    auto sAa = [&](int st) { return base + (uint32_t)st * A_STG; };
    auto sBa = [&](int st) { return base + NSTG * A_STG + (uint32_t)st * B_STG; };

    const int t = threadIdx.x;
    const int lane = t & 31;
    const int wid = t >> 5;            // 0..15
    const int wm = (wid >> 2) * 32;    // 0,32,64,96
    const int wn = (wid & 3) * 64;     // 0,64,128,192
    const int bm = blockIdx.y * 128;
    const int bn = blockIdx.x * 256;
    const int z = blockIdx.z;

    const float* A32 = (z == 0) ? Aq : (z == 1) ? Ak : Av;
    const __half* Bw = W16 + (size_t)z * DD * DD;
    __half* outp = (z == 0) ? qs : (z == 1) ? ks : vs;
    const float mult = (z == 0) ? QMULT : 1.0f;

    // A loader: 4 threads/row (128 rows), each 8 fp32 -> 8 fp16 (one STS.v4)
    const int arow = t >> 2;           // 0..127
    const int acol = (t & 3) * 8;      // 0,8,16,24
    const float* Ag32 = A32 + (size_t)(bm + arow) * DD + acol;
    const uint32_t asoff = (uint32_t)arow * LD2 + (t & 3) * 16;

    // B loader: 2 threads/row (256 rows), each two 16B cp.async
    const int brow = t >> 1;           // 0..255
    const int bseg = t & 1;
    const __half* Bg = Bw + (size_t)(bn + brow) * DD + bseg * 16;
    const uint32_t bsoff = (uint32_t)brow * LD2 + bseg * 32;

    float4 f0, f1;
    auto ldgA = [&](int kt) {
        const float4* p = reinterpret_cast<const float4*>(Ag32 + kt * 32);
        f0 = p[0]; f1 = p[1];
    };
    auto stsA = [&](int st) {
        uint32_t h0 = pack_h2(f0.x, f0.y), h1 = pack_h2(f0.z, f0.w);
        uint32_t h2 = pack_h2(f1.x, f1.y), h3 = pack_h2(f1.z, f1.w);
        asm volatile("st.shared.v4.b32 [%0], {%1,%2,%3,%4};"
                     :: "r"(sAa(st) + asoff), "r"(h0), "r"(h1), "r"(h2), "r"(h3)
                     : "memory");
    };
    auto ldB = [&](int st, int kt) {
        const int k0 = kt * 32;
        cp16(sBa(st) + bsoff,      Bg + k0);
        cp16(sBa(st) + bsoff + 16, Bg + k0 + 8);
        cp_commit();
    };

    const uint32_t aoff = (uint32_t)(wm + (lane & 15)) * LD2 + ((lane >> 4) << 4);
    const uint32_t boff = (uint32_t)(wn + (lane & 7) + ((lane >> 4) << 3)) * LD2
                        + (((lane >> 3) & 1) << 4);

    float d[2][8][4];
#pragma unroll
    for (int i = 0; i < 2; i++)
#pragma unroll
        for (int j = 0; j < 8; j++)
#pragma unroll
            for (int r = 0; r < 4; r++) d[i][j][r] = 0.0f;

    auto comp = [&](int st) {
        uint32_t a[2][2][4];   // [mf][kf]
        uint32_t b[8][2][2];   // [nf][kf]
#pragma unroll
        for (int mf = 0; mf < 2; mf++)
#pragma unroll
            for (int kf = 0; kf < 2; kf++)
                ldm_x4(a[mf][kf], sAa(st) + aoff + mf * 16 * LD2 + kf * 32);
#pragma unroll
        for (int ng = 0; ng < 4; ng++)
#pragma unroll
            for (int kf = 0; kf < 2; kf++) {
                uint32_t r[4];
                ldm_x4(r, sBa(st) + boff + ng * 16 * LD2 + kf * 32);
                b[2 * ng + 0][kf][0] = r[0]; b[2 * ng + 0][kf][1] = r[1];
                b[2 * ng + 1][kf][0] = r[2]; b[2 * ng + 1][kf][1] = r[3];
            }
#pragma unroll
        for (int mf = 0; mf < 2; mf++)
#pragma unroll
            for (int nf = 0; nf < 8; nf++) {
                mma16816(d[mf][nf], a[mf][0], b[nf][0]);
                mma16816(d[mf][nf], a[mf][1], b[nf][1]);
            }
    };

    // prologue: chunks 0..3 staged (stages 0..3), 4 commits
    ldgA(0); stsA(0); ldB(0, 0);
    ldgA(1); stsA(1); ldB(1, 1);
    ldgA(2); stsA(2); ldB(2, 2);
    ldgA(3); stsA(3); ldB(3, 3);

    for (int p = 0; p < 16; ++p) {
        if (p < 15) cp_wait<2>(); else cp_wait<0>();
        __syncthreads();
        const int c2 = 2 * p + 4, c3 = 2 * p + 5;
        if (p < 14) { ldgA(c2); ldB(c2 % NSTG, c2); ldB(c3 % NSTG, c3); }
        comp((2 * p) % NSTG);
        if (p < 14) { stsA(c2 % NSTG); ldgA(c3); }
        comp((2 * p + 1) % NSTG);
        if (p < 14) stsA(c3 % NSTG);
    }

    // Epilogue: warp owns one head (wn = 64 consecutive n)
    const int hh = (bn + wn) >> 6;
    const int hd0 = 2 * (lane & 3);
    const int mrow = bm + wm + (lane >> 2);
#pragma unroll
    for (int mf = 0; mf < 2; mf++) {
#pragma unroll
        for (int half = 0; half < 2; half++) {
            const int m = mrow + mf * 16 + half * 8;
            const int b = m >> 11;
            const int s = m & (SS - 1);
            __half* bp = outp + (((size_t)b * HH + hh) * SS + s) * 64 + hd0;
#pragma unroll
            for (int nf = 0; nf < 8; nf++) {
                *reinterpret_cast<uint32_t*>(bp + nf * 8) =
                    pack_h2(d[mf][nf][half * 2 + 0] * mult,
                            d[mf][nf][half * 2 + 1] * mult);
            }
        }
    }
}

// ---------------------------------------------------------------------------
// Output GEMM: A = fp16 ctx, B = Wo fp16 (both cp.async), bias, fp32 out.
// grid (4, 32), 512 threads, 6-stage ring, 2 chunks per barrier.
// ---------------------------------------------------------------------------
__global__ __launch_bounds__(512, 1) void gemm_out(const __half* __restrict__ A16,
                                                   const __half* __restrict__ W16,
                                                   const float* __restrict__ bias,
                                                   float* __restrict__ out) {
    extern __shared__ __align__(16) __half dsm[];
    const uint32_t base = smem_u32(dsm);
    auto sAa = [&](int st) { return base + (uint32_t)st * A_STG; };
    auto sBa = [&](int st) { return base + NSTG * A_STG + (uint32_t)st * B_STG; };

    const int t = threadIdx.x;
    const int lane = t & 31;
    const int wid = t >> 5;
    const int wm = (wid >> 2) * 32;
    const int wn = (wid & 3) * 64;
    const int bm = blockIdx.y * 128;
    const int bn = blockIdx.x * 256;

    // A loader: 4 threads/row, one cp16 each (128 rows x 64B)
    const int arow = t >> 2;
    const int aseg = t & 3;
    const __half* Ag = A16 + (size_t)(bm + arow) * DD + aseg * 8;
    const uint32_t asoff = (uint32_t)arow * LD2 + aseg * 16;
    // B loader: 2 threads/row, two cp16 each (256 rows x 64B)
    const int brow = t >> 1;
    const int bseg = t & 1;
    const __half* Bg = W16 + (size_t)(bn + brow) * DD + bseg * 16;
    const uint32_t bsoff = (uint32_t)brow * LD2 + bseg * 32;

    auto load_tile = [&](int st, int kt) {
        const int k0 = kt * 32;
        cp16(sAa(st) + asoff, Ag + k0);
        cp16(sBa(st) + bsoff,      Bg + k0);
        cp16(sBa(st) + bsoff + 16, Bg + k0 + 8);
        cp_commit();
    };

    const uint32_t aoff = (uint32_t)(wm + (lane & 15)) * LD2 + ((lane >> 4) << 4);
    const uint32_t boff = (uint32_t)(wn + (lane & 7) + ((lane >> 4) << 3)) * LD2
                        + (((lane >> 3) & 1) << 4);

    float d[2][8][4];
#pragma unroll
    for (int i = 0; i < 2; i++)
#pragma unroll
        for (int j = 0; j < 8; j++)
#pragma unroll
            for (int r = 0; r < 4; r++) d[i][j][r] = 0.0f;

    auto comp = [&](int st) {
        uint32_t a[2][2][4];
        uint32_t b[8][2][2];
#pragma unroll
        for (int mf = 0; mf < 2; mf++)
#pragma unroll
            for (int kf = 0; kf < 2; kf++)
                ldm_x4(a[mf][kf], sAa(st) + aoff + mf * 16 * LD2 + kf * 32);
#pragma unroll
        for (int ng = 0; ng < 4; ng++)
#pragma unroll
            for (int kf = 0; kf < 2; kf++) {
                uint32_t r[4];
                ldm_x4(r, sBa(st) + boff + ng * 16 * LD2 + kf * 32);
                b[2 * ng + 0][kf][0] = r[0]; b[2 * ng + 0][kf][1] = r[1];
                b[2 * ng + 1][kf][0] = r[2]; b[2 * ng + 1][kf][1] = r[3];
            }
#pragma unroll
        for (int mf = 0; mf < 2; mf++)
#pragma unroll
            for (int nf = 0; nf < 8; nf++) {
                mma16816(d[mf][nf], a[mf][0], b[nf][0]);
                mma16816(d[mf][nf], a[mf][1], b[nf][1]);
            }
    };

    load_tile(0, 0); load_tile(1, 1); load_tile(2, 2); load_tile(3, 3);

    for (int p = 0; p < 16; ++p) {
        if (p < 15) cp_wait<2>(); else cp_wait<0>();
        __syncthreads();
        const int c2 = 2 * p + 4, c3 = 2 * p + 5;
        if (p < 14) { load_tile(c2 % NSTG, c2); load_tile(c3 % NSTG, c3); }
        comp((2 * p) % NSTG);
        comp((2 * p + 1) % NSTG);
    }

    const int mrow = bm + wm + (lane >> 2);
    const int ncol0 = bn + wn + 2 * (lane & 3);
#pragma unroll
    for (int mf = 0; mf < 2; mf++) {
#pragma unroll
        for (int half = 0; half < 2; half++) {
            const int m = mrow + mf * 16 + half * 8;
            float* orow = out + (size_t)m * DD;
#pragma unroll
            for (int nf = 0; nf < 8; nf++) {
                const int n = ncol0 + nf * 8;
                float2 o;
                o.x = d[mf][nf][half * 2 + 0] + bias[n];
                o.y = d[mf][nf][half * 2 + 1] + bias[n + 1];
                *reinterpret_cast<float2*>(orow + n) = o;
            }
        }
    }
}

// ---------------------------------------------------------------------------
// Tensor-core flash attention with 1-ahead ldmatrix prefetch.
// grid (S/128, B*H), 256 threads (8 warps x 16 q rows), 2 CTAs/SM.
// ---------------------------------------------------------------------------
#define LDK 72    // K/V/Q smem row stride in halfwords (144B)

__global__ __launch_bounds__(256, 2) void attn_mma() {
    __shared__ __align__(16) __half smem[2 * 2 * 64 * LDK];  // 36,864 B

    const int t = threadIdx.x;
    const int lane = t & 31;
    const int w = t >> 5;
    const int bh = blockIdx.y;
    const int q0 = blockIdx.x * 128;

    const uint32_t sbase = smem_u32(smem);
    auto sK = [&](int buf) { return sbase + (uint32_t)(buf * 2 + 0) * (64 * LDK * 2); };
    auto sV = [&](int buf) { return sbase + (uint32_t)(buf * 2 + 1) * (64 * LDK * 2); };

    const __half* Qg = g_Qs + ((size_t)bh * SS + q0) * 64;
#pragma unroll
    for (int i = 0; i < 4; i++) {
        int idx = i * 256 + t;
        int row = idx >> 3, ch = idx & 7;
        cp16(sbase + row * (LDK * 2) + ch * 16, Qg + (size_t)row * 64 + ch * 8);
    }
    cp_commit(); cp_wait<0>();
    __syncthreads();

    uint32_t qa[4][4];
    const uint32_t aoff = (uint32_t)(w * 16 + (lane & 15)) * (LDK * 2) + ((lane >> 4) << 4);
#pragma unroll
    for (int kf = 0; kf < 4; kf++) ldm_x4(qa[kf], sbase + aoff + kf * 32);
    __syncthreads();

    float o[8][4];
#pragma unroll
    for (int f = 0; f < 8; f++)
#pragma unroll
        for (int r = 0; r < 4; r++) o[f][r] = 0.0f;
    float mrow[2] = { -1e30f, -1e30f };
    float lsum[2] = { 0.0f, 0.0f };

    const __half* Kg = g_Ks + (size_t)bh * SS * 64;
    const __half* Vg = g_Vs + (size_t)bh * SS * 64;

    const uint32_t boff = (uint32_t)((lane & 7) + ((lane >> 4) << 3)) * (LDK * 2)
                        + (((lane >> 3) & 1) << 4);
    const uint32_t voff = (uint32_t)(lane & 15) * (LDK * 2) + ((lane >> 4) << 4);

    auto issueKV = [&](int buf, int it) {
        const int k0 = it * 64;
#pragma unroll
        for (int i = 0; i < 2; i++) {
            int idx = i * 256 + t;
            int row = idx >> 3, ch = idx & 7;
            cp16(sK(buf) + row * (LDK * 2) + ch * 16, Kg + ((size_t)(k0 + row)) * 64 + ch * 8);
            cp16(sV(buf) + row * (LDK * 2) + ch * 16, Vg + ((size_t)(k0 + row)) * 64 + ch * 8);
        }
        cp_commit();
    };

    constexpr int NT = SS / 64;   // 32
    issueKV(0, 0);
    int buf = 0;
    for (int it = 0; it < NT; ++it) {
        if (it + 1 < NT) { issueKV(buf ^ 1, it + 1); cp_wait<1>(); }
        else cp_wait<0>();
        __syncthreads();

        // ---- S = Q K^T with 1-ahead K-fragment prefetch ----
        float s[8][4];
#pragma unroll
        for (int f = 0; f < 8; f++)
#pragma unroll
            for (int r = 0; r < 4; r++) s[f][r] = 0.0f;
        {
            uint32_t bk[2][4];
            ldm_x4(bk[0], sK(buf) + boff);   // (kf=0, nc=0)
#pragma unroll
            for (int idx = 0; idx < 16; idx++) {
                const int kf = idx >> 2, nc = idx & 3;
                if (idx < 15) {
                    const int kf2 = (idx + 1) >> 2, nc2 = (idx + 1) & 3;
                    ldm_x4(bk[(idx + 1) & 1],
                           sK(buf) + boff + nc2 * 16 * (LDK * 2) + kf2 * 32);
                }
                mma16816(s[2 * nc],     qa[kf], bk[idx & 1] + 0);
                mma16816(s[2 * nc + 1], qa[kf], bk[idx & 1] + 2);
            }
        }

        // ---- online softmax ----
        float tm0 = -1e30f, tm1 = -1e30f;
#pragma unroll
        for (int f = 0; f < 8; f++) {
            tm0 = fmaxf(tm0, fmaxf(s[f][0], s[f][1]));
            tm1 = fmaxf(tm1, fmaxf(s[f][2], s[f][3]));
        }
        tm0 = fmaxf(tm0, __shfl_xor_sync(0xffffffffu, tm0, 1));
        tm0 = fmaxf(tm0, __shfl_xor_sync(0xffffffffu, tm0, 2));
        tm1 = fmaxf(tm1, __shfl_xor_sync(0xffffffffu, tm1, 1));
        tm1 = fmaxf(tm1, __shfl_xor_sync(0xffffffffu, tm1, 2));
        const float mn0 = fmaxf(mrow[0], tm0);
        const float mn1 = fmaxf(mrow[1], tm1);
        const float sc0 = ex2f(mrow[0] - mn0);
        const float sc1 = ex2f(mrow[1] - mn1);
        mrow[0] = mn0; mrow[1] = mn1;
        lsum[0] *= sc0; lsum[1] *= sc1;
#pragma unroll
        for (int f = 0; f < 8; f++) {
            o[f][0] *= sc0; o[f][1] *= sc0;
            o[f][2] *= sc1; o[f][3] *= sc1;
        }

        // ---- P = exp2(S - m), pack into A-fragments ----
        uint32_t ph[4][4];
#pragma unroll
        for (int kf = 0; kf < 4; kf++) {
#pragma unroll
            for (int j = 0; j < 2; j++) {
                float* sf = s[2 * kf + j];
                float p0 = ex2f(sf[0] - mn0);
                float p1 = ex2f(sf[1] - mn0);
                float p2 = ex2f(sf[2] - mn1);
                float p3 = ex2f(sf[3] - mn1);
                lsum[0] += p0 + p1;
                lsum[1] += p2 + p3;
                ph[kf][2 * j + 0] = pack_h2(p0, p1);
                ph[kf][2 * j + 1] = pack_h2(p2, p3);
            }
        }

        // ---- O += P V with 1-ahead V-fragment prefetch ----
        {
            uint32_t bv[2][4];
            ldm_x4_t(bv[0], sV(buf) + voff);   // (kf=0, nc=0)
#pragma unroll
            for (int idx = 0; idx < 16; idx++) {
                const int kf = idx >> 2, nc = idx & 3;
                if (idx < 15) {
                    const int kf2 = (idx + 1) >> 2, nc2 = (idx + 1) & 3;
                    ldm_x4_t(bv[(idx + 1) & 1],
                             sV(buf) + voff + kf2 * 16 * (LDK * 2) + nc2 * 32);
                }
                mma16816(o[2 * nc],     ph[kf], bv[idx & 1] + 0);
                mma16816(o[2 * nc + 1], ph[kf], bv[idx & 1] + 2);
            }
        }
        __syncthreads();
        buf ^= 1;
    }

    lsum[0] += __shfl_xor_sync(0xffffffffu, lsum[0], 1);
    lsum[0] += __shfl_xor_sync(0xffffffffu, lsum[0], 2);
    lsum[1] += __shfl_xor_sync(0xffffffffu, lsum[1], 1);
    lsum[1] += __shfl_xor_sync(0xffffffffu, lsum[1], 2);
    const float inv0 = 1.0f / lsum[0];
    const float inv1 = 1.0f / lsum[1];

    const int b = bh >> 4;
    const int h = bh & (HH - 1);
    const int r0 = q0 + w * 16 + (lane >> 2);
    const int col = h * HDD + 2 * (lane & 3);
    __half* O0 = g_ctxh + ((size_t)b * SS + r0) * DD + col;
    __half* O1 = g_ctxh + ((size_t)b * SS + r0 + 8) * DD + col;
#pragma unroll
    for (int f = 0; f < 8; f++) {
        *reinterpret_cast<uint32_t*>(O0 + f * 8) = pack_h2(o[f][0] * inv0, o[f][1] * inv0);
        *reinterpret_cast<uint32_t*>(O1 + f * 8) = pack_h2(o[f][2] * inv1, o[f][3] * inv1);
    }
}

// ---------------------------------------------------------------------------
// Launch
// ---------------------------------------------------------------------------
extern "C" void kernel_launch(void* const* d_in, const int* in_sizes, int n_in,
                              void* d_out, int out_size) {
    const float* query = (const float*)d_in[0];
    const float* key_i = (const float*)d_in[1];
    const float* value = (const float*)d_in[2];
    const float* Wq = (const float*)d_in[3];
    const float* Wk = (const float*)d_in[4];
    const float* Wv = (const float*)d_in[5];
    const float* Wo = (const float*)d_in[6];
    const float* bo = (const float*)d_in[7];
    float* out = (float*)d_out;

    __half *qs, *ks, *vs, *ctxh, *w16;
    cudaGetSymbolAddress((void**)&qs, g_Qs);
    cudaGetSymbolAddress((void**)&ks, g_Ks);
    cudaGetSymbolAddress((void**)&vs, g_Vs);
    cudaGetSymbolAddress((void**)&ctxh, g_ctxh);
    cudaGetSymbolAddress((void**)&w16, g_W16);

    static bool attr_done = false;
    if (!attr_done) {
        cudaFuncSetAttribute(gemm_qkv, cudaFuncAttributeMaxDynamicSharedMemorySize, GEMM_SMEM);
        cudaFuncSetAttribute(gemm_out, cudaFuncAttributeMaxDynamicSharedMemorySize, GEMM_SMEM);
        attr_done = true;
    }

    // 1. all weights -> fp16
    conv_w<<<4 * (DD * DD / 4) / 256, 256>>>(Wq, Wk, Wv, Wo, w16);

    // 2. Q,K,V projections (fused A conversion), 128x256 tiles
    dim3 qgrid(DD / 256, MROWS / 128, 3);   // (4, 32, 3)
    gemm_qkv<<<qgrid, 512, GEMM_SMEM>>>(query, key_i, value, w16, qs, ks, vs);

    // 3. attention -> fp16 ctx
    dim3 agrid(SS / 128, BB * HH);
    attn_mma<<<agrid, 256>>>();

    // 4. output projection, 128x256 tiles
    dim3 ogrid(DD / 256, MROWS / 128);      // (4, 32)
    gemm_out<<<ogrid, 512, GEMM_SMEM>>>(ctxh, w16 + (size_t)3 * DD * DD, bo, out);
}

// round 14
// speedup vs baseline: 1.0256x; 1.0256x over previous
#include <cuda_runtime.h>
#include <cuda_fp16.h>
#include <cstdint>

// Problem constants
#define BB 2
#define SS 2048
#define DD 1024
#define HH 16
#define HDD 64
#define MROWS (BB * SS)          // 4096
static constexpr float QMULT = 1.4426950408889634f / 32.0f;  // log2(e)/sqrt(D)

// ---------------------------------------------------------------------------
// Device scratch
// ---------------------------------------------------------------------------
__device__ __half g_Qs[(size_t)BB * HH * SS * 64];   // [BH,S,64] (pre-scaled)
__device__ __half g_Ks[(size_t)BB * HH * SS * 64];
__device__ __half g_Vs[(size_t)BB * HH * SS * 64];
__device__ __half g_ctxh[(size_t)MROWS * DD];        // [B*S, D] fp16 ctx
__device__ __half g_W16[(size_t)4 * DD * DD];        // Wq|Wk|Wv|Wo fp16

// ---------------------------------------------------------------------------
// Helpers (baseline PTX only: cp.async / ldmatrix / mma.sync)
// ---------------------------------------------------------------------------
__device__ __forceinline__ uint32_t smem_u32(const void* p) {
    uint32_t a;
    asm("{ .reg .u64 t; cvta.to.shared.u64 t, %1; cvt.u32.u64 %0, t; }" : "=r"(a) : "l"(p));
    return a;
}
__device__ __forceinline__ void cp16(uint32_t s, const void* g) {
    asm volatile("cp.async.cg.shared.global [%0], [%1], 16;" :: "r"(s), "l"(g));
}
__device__ __forceinline__ void cp_commit() {
    asm volatile("cp.async.commit_group;" ::: "memory");
}
template <int N>
__device__ __forceinline__ void cp_wait() {
    asm volatile("cp.async.wait_group %0;" :: "n"(N) : "memory");
}
__device__ __forceinline__ void ldm_x4(uint32_t* r, uint32_t addr) {
    asm volatile("ldmatrix.sync.aligned.m8n8.x4.shared.b16 {%0,%1,%2,%3}, [%4];"
                 : "=r"(r[0]), "=r"(r[1]), "=r"(r[2]), "=r"(r[3]) : "r"(addr));
}
__device__ __forceinline__ void ldm_x4_t(uint32_t* r, uint32_t addr) {
    asm volatile("ldmatrix.sync.aligned.m8n8.x4.trans.shared.b16 {%0,%1,%2,%3}, [%4];"
                 : "=r"(r[0]), "=r"(r[1]), "=r"(r[2]), "=r"(r[3]) : "r"(addr));
}
__device__ __forceinline__ void mma16816(float* d, const uint32_t* a, const uint32_t* b) {
    asm volatile(
        "mma.sync.aligned.m16n8k16.row.col.f32.f16.f16.f32 "
        "{%0,%1,%2,%3}, {%4,%5,%6,%7}, {%8,%9}, {%0,%1,%2,%3};"
        : "+f"(d[0]), "+f"(d[1]), "+f"(d[2]), "+f"(d[3])
        : "r"(a[0]), "r"(a[1]), "r"(a[2]), "r"(a[3]), "r"(b[0]), "r"(b[1]));
}
__device__ __forceinline__ float ex2f(float x) {
    float r;
    asm("ex2.approx.ftz.f32 %0, %1;" : "=f"(r) : "f"(x));
    return r;
}
__device__ __forceinline__ uint32_t pack_h2(float x, float y) {
    __half2 h2; h2.x = __float2half_rn(x); h2.y = __float2half_rn(y);
    return *reinterpret_cast<uint32_t*>(&h2);
}

// ---------------------------------------------------------------------------
// Convert all 4 weight matrices fp32->fp16 in one launch.
// ---------------------------------------------------------------------------
__global__ __launch_bounds__(256) void conv_w(const float* __restrict__ w0,
                                              const float* __restrict__ w1,
                                              const float* __restrict__ w2,
                                              const float* __restrict__ w3,
                                              __half* __restrict__ out) {
    int idx = blockIdx.x * 256 + threadIdx.x;      // float4 units
    const int per = DD * DD / 4;                   // 262144
    int wsel = idx / per;
    int off = idx - wsel * per;
    const float* src = (wsel == 0) ? w0 : (wsel == 1) ? w1 : (wsel == 2) ? w2 : w3;
    float4 x = reinterpret_cast<const float4*>(src)[off];
    __half2 a; a.x = __float2half_rn(x.x); a.y = __float2half_rn(x.y);
    __half2 b; b.x = __float2half_rn(x.z); b.y = __float2half_rn(x.w);
    __half2* o = reinterpret_cast<__half2*>(out + (size_t)wsel * DD * DD) + off * 2;
    o[0] = a; o[1] = b;
}

// ---------------------------------------------------------------------------
// GEMM geometry (Round-12 winner): CTA tile 128(M) x 256(N), 512 threads =
// 16 warps (4m x 4n), warp tile 32x64. 4-stage smem ring, loads 2 chunks
// ahead, ONE barrier per chunk, &3 stage indexing.
// ---------------------------------------------------------------------------
#define LDHW 40                  // smem row stride in halfwords (80 bytes)
#define LD2  (LDHW * 2)
#define A_STG ((uint32_t)(128 * LD2))    // 10240 B per A stage
#define B_STG ((uint32_t)(256 * LD2))    // 20480 B per B stage
#define GEMM_SMEM (4 * (128 * LD2) + 4 * (256 * LD2))   // 122880 B

// ---------------------------------------------------------------------------
// QKV GEMM (fused A-side fp32->fp16): grid (4, 32, 3), 512 threads.
// ---------------------------------------------------------------------------
__global__ __launch_bounds__(512, 1) void gemm_qkv(const float* __restrict__ Aq,
                                                   const float* __restrict__ Ak,
                                                   const float* __restrict__ Av,
                                                   const __half* __restrict__ W16,
                                                   __half* __restrict__ qs,
                                                   __half* __restrict__ ks,
                                                   __half* __restrict__ vs) {
    constexpr int NK = DD / 32;   // 32
    extern __shared__ __align__(16) __half dsm[];
    const uint32_t base = smem_u32(dsm);
    auto sAa = [&](int st) { return base + (uint32_t)st * A_STG; };
    auto sBa = [&](int st) { return base + 4 * A_STG + (uint32_t)st * B_STG; };

    const int t = threadIdx.x;
    const int lane = t & 31;
    const int wid = t >> 5;            // 0..15
    const int wm = (wid >> 2) * 32;    // 0,32,64,96
    const int wn = (wid & 3) * 64;     // 0,64,128,192
    const int bm = blockIdx.y * 128;
    const int bn = blockIdx.x * 256;
    const int z = blockIdx.z;

    const float* A32 = (z == 0) ? Aq : (z == 1) ? Ak : Av;
    const __half* Bw = W16 + (size_t)z * DD * DD;
    __half* outp = (z == 0) ? qs : (z == 1) ? ks : vs;
    const float mult = (z == 0) ? QMULT : 1.0f;

    // A loader: 4 threads/row (128 rows), each 8 fp32 -> 8 fp16 (one STS.v4)
    const int arow = t >> 2;           // 0..127
    const int acol = (t & 3) * 8;      // 0,8,16,24
    const float* Ag32 = A32 + (size_t)(bm + arow) * DD + acol;
    const uint32_t asoff = (uint32_t)arow * LD2 + (t & 3) * 16;

    // B loader: 2 threads/row (256 rows), each two 16B cp.async
    const int brow = t >> 1;           // 0..255
    const int bseg = t & 1;
    const __half* Bg = Bw + (size_t)(bn + brow) * DD + bseg * 16;
    const uint32_t bsoff = (uint32_t)brow * LD2 + bseg * 32;

    float4 f0, f1;
    auto ldgA = [&](int kt) {
        const float4* p = reinterpret_cast<const float4*>(Ag32 + kt * 32);
        f0 = p[0]; f1 = p[1];
    };
    auto stsA = [&](int st) {
        uint32_t h0 = pack_h2(f0.x, f0.y), h1 = pack_h2(f0.z, f0.w);
        uint32_t h2 = pack_h2(f1.x, f1.y), h3 = pack_h2(f1.z, f1.w);
        asm volatile("st.shared.v4.b32 [%0], {%1,%2,%3,%4};"
                     :: "r"(sAa(st) + asoff), "r"(h0), "r"(h1), "r"(h2), "r"(h3)
                     : "memory");
    };
    auto ldB = [&](int st, int kt) {
        const int k0 = kt * 32;
        cp16(sBa(st) + bsoff,      Bg + k0);
        cp16(sBa(st) + bsoff + 16, Bg + k0 + 8);
        cp_commit();
    };

    const uint32_t aoff = (uint32_t)(wm + (lane & 15)) * LD2 + ((lane >> 4) << 4);
    const uint32_t boff = (uint32_t)(wn + (lane & 7) + ((lane >> 4) << 3)) * LD2
                        + (((lane >> 3) & 1) << 4);

    float d[2][8][4];
#pragma unroll
    for (int i = 0; i < 2; i++)
#pragma unroll
        for (int j = 0; j < 8; j++)
#pragma unroll
            for (int r = 0; r < 4; r++) d[i][j][r] = 0.0f;

    // prologue: chunks 0,1 staged
    ldgA(0); ldB(0, 0); stsA(0);
    ldgA(1); ldB(1, 1); stsA(1);

    for (int kt = 0; kt < NK; ++kt) {
        const int st = kt & 3;
        if (kt + 2 < NK) { ldgA(kt + 2); ldB((kt + 2) & 3, kt + 2); }
        if (kt + 2 < NK) cp_wait<2>();
        else if (kt + 1 < NK) cp_wait<1>();
        else cp_wait<0>();
        __syncthreads();

        uint32_t a[2][2][4];   // [mf][kf]
        uint32_t b[8][2][2];   // [nf][kf]
#pragma unroll
        for (int mf = 0; mf < 2; mf++)
#pragma unroll
            for (int kf = 0; kf < 2; kf++)
                ldm_x4(a[mf][kf], sAa(st) + aoff + mf * 16 * LD2 + kf * 32);
#pragma unroll
        for (int ng = 0; ng < 4; ng++)
#pragma unroll
            for (int kf = 0; kf < 2; kf++) {
                uint32_t r[4];
                ldm_x4(r, sBa(st) + boff + ng * 16 * LD2 + kf * 32);
                b[2 * ng + 0][kf][0] = r[0]; b[2 * ng + 0][kf][1] = r[1];
                b[2 * ng + 1][kf][0] = r[2]; b[2 * ng + 1][kf][1] = r[3];
            }
#pragma unroll
        for (int mf = 0; mf < 2; mf++)
#pragma unroll
            for (int nf = 0; nf < 8; nf++) {
                mma16816(d[mf][nf], a[mf][0], b[nf][0]);
                mma16816(d[mf][nf], a[mf][1], b[nf][1]);
            }

        if (kt + 2 < NK) stsA((kt + 2) & 3);  // stage last read 2 barriers ago
    }

    // Epilogue: warp owns one head (wn = 64 consecutive n)
    const int hh = (bn + wn) >> 6;
    const int hd0 = 2 * (lane & 3);
    const int mrow = bm + wm + (lane >> 2);
#pragma unroll
    for (int mf = 0; mf < 2; mf++) {
#pragma unroll
        for (int half = 0; half < 2; half++) {
            const int m = mrow + mf * 16 + half * 8;
            const int b = m >> 11;
            const int s = m & (SS - 1);
            __half* bp = outp + (((size_t)b * HH + hh) * SS + s) * 64 + hd0;
#pragma unroll
            for (int nf = 0; nf < 8; nf++) {
                *reinterpret_cast<uint32_t*>(bp + nf * 8) =
                    pack_h2(d[mf][nf][half * 2 + 0] * mult,
                            d[mf][nf][half * 2 + 1] * mult);
            }
        }
    }
}

// ---------------------------------------------------------------------------
// Output GEMM: A = fp16 ctx, B = Wo fp16 (both cp.async), bias, fp32 out.
// grid (4, 32), 512 threads. (Round-12 winner.)
// ---------------------------------------------------------------------------
__global__ __launch_bounds__(512, 1) void gemm_out(const __half* __restrict__ A16,
                                                   const __half* __restrict__ W16,
                                                   const float* __restrict__ bias,
                                                   float* __restrict__ out) {
    constexpr int NK = DD / 32;   // 32
    extern __shared__ __align__(16) __half dsm[];
    const uint32_t base = smem_u32(dsm);
    auto sAa = [&](int st) { return base + (uint32_t)st * A_STG; };
    auto sBa = [&](int st) { return base + 4 * A_STG + (uint32_t)st * B_STG; };

    const int t = threadIdx.x;
    const int lane = t & 31;
    const int wid = t >> 5;
    const int wm = (wid >> 2) * 32;
    const int wn = (wid & 3) * 64;
    const int bm = blockIdx.y * 128;
    const int bn = blockIdx.x * 256;

    // A loader: 4 threads/row, one cp16 each (128 rows x 64B)
    const int arow = t >> 2;
    const int aseg = t & 3;
    const __half* Ag = A16 + (size_t)(bm + arow) * DD + aseg * 8;
    const uint32_t asoff = (uint32_t)arow * LD2 + aseg * 16;
    // B loader: 2 threads/row, two cp16 each (256 rows x 64B)
    const int brow = t >> 1;
    const int bseg = t & 1;
    const __half* Bg = W16 + (size_t)(bn + brow) * DD + bseg * 16;
    const uint32_t bsoff = (uint32_t)brow * LD2 + bseg * 32;

    auto load_tile = [&](int st, int kt) {
        const int k0 = kt * 32;
        cp16(sAa(st) + asoff, Ag + k0);
        cp16(sBa(st) + bsoff,      Bg + k0);
        cp16(sBa(st) + bsoff + 16, Bg + k0 + 8);
        cp_commit();
    };

    const uint32_t aoff = (uint32_t)(wm + (lane & 15)) * LD2 + ((lane >> 4) << 4);
    const uint32_t boff = (uint32_t)(wn + (lane & 7) + ((lane >> 4) << 3)) * LD2
                        + (((lane >> 3) & 1) << 4);

    float d[2][8][4];
#pragma unroll
    for (int i = 0; i < 2; i++)
#pragma unroll
        for (int j = 0; j < 8; j++)
#pragma unroll
            for (int r = 0; r < 4; r++) d[i][j][r] = 0.0f;

    load_tile(0, 0);
    load_tile(1, 1);

    for (int kt = 0; kt < NK; ++kt) {
        const int st = kt & 3;
        if (kt + 2 < NK) load_tile((kt + 2) & 3, kt + 2);
        if (kt + 2 < NK) cp_wait<2>();
        else if (kt + 1 < NK) cp_wait<1>();
        else cp_wait<0>();
        __syncthreads();

        uint32_t a[2][2][4];
        uint32_t b[8][2][2];
#pragma unroll
        for (int mf = 0; mf < 2; mf++)
#pragma unroll
            for (int kf = 0; kf < 2; kf++)
                ldm_x4(a[mf][kf], sAa(st) + aoff + mf * 16 * LD2 + kf * 32);
#pragma unroll
        for (int ng = 0; ng < 4; ng++)
#pragma unroll
            for (int kf = 0; kf < 2; kf++) {
                uint32_t r[4];
                ldm_x4(r, sBa(st) + boff + ng * 16 * LD2 + kf * 32);
                b[2 * ng + 0][kf][0] = r[0]; b[2 * ng + 0][kf][1] = r[1];
                b[2 * ng + 1][kf][0] = r[2]; b[2 * ng + 1][kf][1] = r[3];
            }
#pragma unroll
        for (int mf = 0; mf < 2; mf++)
#pragma unroll
            for (int nf = 0; nf < 8; nf++) {
                mma16816(d[mf][nf], a[mf][0], b[nf][0]);
                mma16816(d[mf][nf], a[mf][1], b[nf][1]);
            }
    }

    const int mrow = bm + wm + (lane >> 2);
    const int ncol0 = bn + wn + 2 * (lane & 3);
#pragma unroll
    for (int mf = 0; mf < 2; mf++) {
#pragma unroll
        for (int half = 0; half < 2; half++) {
            const int m = mrow + mf * 16 + half * 8;
            float* orow = out + (size_t)m * DD;
#pragma unroll
            for (int nf = 0; nf < 8; nf++) {
                const int n = ncol0 + nf * 8;
                float2 o;
                o.x = d[mf][nf][half * 2 + 0] + bias[n];
                o.y = d[mf][nf][half * 2 + 1] + bias[n + 1];
                *reinterpret_cast<float2*>(orow + n) = o;
            }
        }
    }
}

// ---------------------------------------------------------------------------
// Tensor-core flash attention with 1-ahead ldmatrix prefetch (Round-13 keep).
// grid (S/128, B*H), 256 threads (8 warps x 16 q rows), 2 CTAs/SM.
// ---------------------------------------------------------------------------
#define LDK 72    // K/V/Q smem row stride in halfwords (144B)

__global__ __launch_bounds__(256, 2) void attn_mma() {
    __shared__ __align__(16) __half smem[2 * 2 * 64 * LDK];  // 36,864 B

    const int t = threadIdx.x;
    const int lane = t & 31;
    const int w = t >> 5;
    const int bh = blockIdx.y;
    const int q0 = blockIdx.x * 128;

    const uint32_t sbase = smem_u32(smem);
    auto sK = [&](int buf) { return sbase + (uint32_t)(buf * 2 + 0) * (64 * LDK * 2); };
    auto sV = [&](int buf) { return sbase + (uint32_t)(buf * 2 + 1) * (64 * LDK * 2); };

    const __half* Qg = g_Qs + ((size_t)bh * SS + q0) * 64;
#pragma unroll
    for (int i = 0; i < 4; i++) {
        int idx = i * 256 + t;
        int row = idx >> 3, ch = idx & 7;
        cp16(sbase + row * (LDK * 2) + ch * 16, Qg + (size_t)row * 64 + ch * 8);
    }
    cp_commit(); cp_wait<0>();
    __syncthreads();

    uint32_t qa[4][4];
    const uint32_t aoff = (uint32_t)(w * 16 + (lane & 15)) * (LDK * 2) + ((lane >> 4) << 4);
#pragma unroll
    for (int kf = 0; kf < 4; kf++) ldm_x4(qa[kf], sbase + aoff + kf * 32);
    __syncthreads();

    float o[8][4];
#pragma unroll
    for (int f = 0; f < 8; f++)
#pragma unroll
        for (int r = 0; r < 4; r++) o[f][r] = 0.0f;
    float mrow[2] = { -1e30f, -1e30f };
    float lsum[2] = { 0.0f, 0.0f };

    const __half* Kg = g_Ks + (size_t)bh * SS * 64;
    const __half* Vg = g_Vs + (size_t)bh * SS * 64;

    const uint32_t boff = (uint32_t)((lane & 7) + ((lane >> 4) << 3)) * (LDK * 2)
                        + (((lane >> 3) & 1) << 4);
    const uint32_t voff = (uint32_t)(lane & 15) * (LDK * 2) + ((lane >> 4) << 4);

    auto issueKV = [&](int buf, int it) {
        const int k0 = it * 64;
#pragma unroll
        for (int i = 0; i < 2; i++) {
            int idx = i * 256 + t;
            int row = idx >> 3, ch = idx & 7;
            cp16(sK(buf) + row * (LDK * 2) + ch * 16, Kg + ((size_t)(k0 + row)) * 64 + ch * 8);
            cp16(sV(buf) + row * (LDK * 2) + ch * 16, Vg + ((size_t)(k0 + row)) * 64 + ch * 8);
        }
        cp_commit();
    };

    constexpr int NT = SS / 64;   // 32
    issueKV(0, 0);
    int buf = 0;
    for (int it = 0; it < NT; ++it) {
        if (it + 1 < NT) { issueKV(buf ^ 1, it + 1); cp_wait<1>(); }
        else cp_wait<0>();
        __syncthreads();

        // ---- S = Q K^T with 1-ahead K-fragment prefetch ----
        float s[8][4];
#pragma unroll
        for (int f = 0; f < 8; f++)
#pragma unroll
            for (int r = 0; r < 4; r++) s[f][r] = 0.0f;
        {
            uint32_t bk[2][4];
            ldm_x4(bk[0], sK(buf) + boff);   // (kf=0, nc=0)
#pragma unroll
            for (int idx = 0; idx < 16; idx++) {
                const int kf = idx >> 2, nc = idx & 3;
                if (idx < 15) {
                    const int kf2 = (idx + 1) >> 2, nc2 = (idx + 1) & 3;
                    ldm_x4(bk[(idx + 1) & 1],
                           sK(buf) + boff + nc2 * 16 * (LDK * 2) + kf2 * 32);
                }
                mma16816(s[2 * nc],     qa[kf], bk[idx & 1] + 0);
                mma16816(s[2 * nc + 1], qa[kf], bk[idx & 1] + 2);
            }
        }

        // ---- online softmax ----
        float tm0 = -1e30f, tm1 = -1e30f;
#pragma unroll
        for (int f = 0; f < 8; f++) {
            tm0 = fmaxf(tm0, fmaxf(s[f][0], s[f][1]));
            tm1 = fmaxf(tm1, fmaxf(s[f][2], s[f][3]));
        }
        tm0 = fmaxf(tm0, __shfl_xor_sync(0xffffffffu, tm0, 1));
        tm0 = fmaxf(tm0, __shfl_xor_sync(0xffffffffu, tm0, 2));
        tm1 = fmaxf(tm1, __shfl_xor_sync(0xffffffffu, tm1, 1));
        tm1 = fmaxf(tm1, __shfl_xor_sync(0xffffffffu, tm1, 2));
        const float mn0 = fmaxf(mrow[0], tm0);
        const float mn1 = fmaxf(mrow[1], tm1);
        const float sc0 = ex2f(mrow[0] - mn0);
        const float sc1 = ex2f(mrow[1] - mn1);
        mrow[0] = mn0; mrow[1] = mn1;
        lsum[0] *= sc0; lsum[1] *= sc1;
#pragma unroll
        for (int f = 0; f < 8; f++) {
            o[f][0] *= sc0; o[f][1] *= sc0;
            o[f][2] *= sc1; o[f][3] *= sc1;
        }

        // ---- P = exp2(S - m), pack into A-fragments ----
        uint32_t ph[4][4];
#pragma unroll
        for (int kf = 0; kf < 4; kf++) {
#pragma unroll
            for (int j = 0; j < 2; j++) {
                float* sf = s[2 * kf + j];
                float p0 = ex2f(sf[0] - mn0);
                float p1 = ex2f(sf[1] - mn0);
                float p2 = ex2f(sf[2] - mn1);
                float p3 = ex2f(sf[3] - mn1);
                lsum[0] += p0 + p1;
                lsum[1] += p2 + p3;
                ph[kf][2 * j + 0] = pack_h2(p0, p1);
                ph[kf][2 * j + 1] = pack_h2(p2, p3);
            }
        }

        // ---- O += P V with 1-ahead V-fragment prefetch ----
        {
            uint32_t bv[2][4];
            ldm_x4_t(bv[0], sV(buf) + voff);   // (kf=0, nc=0)
#pragma unroll
            for (int idx = 0; idx < 16; idx++) {
                const int kf = idx >> 2, nc = idx & 3;
                if (idx < 15) {
                    const int kf2 = (idx + 1) >> 2, nc2 = (idx + 1) & 3;
                    ldm_x4_t(bv[(idx + 1) & 1],
                             sV(buf) + voff + kf2 * 16 * (LDK * 2) + nc2 * 32);
                }
                mma16816(o[2 * nc],     ph[kf], bv[idx & 1] + 0);
                mma16816(o[2 * nc + 1], ph[kf], bv[idx & 1] + 2);
            }
        }
        __syncthreads();
        buf ^= 1;
    }

    lsum[0] += __shfl_xor_sync(0xffffffffu, lsum[0], 1);
    lsum[0] += __shfl_xor_sync(0xffffffffu, lsum[0], 2);
    lsum[1] += __shfl_xor_sync(0xffffffffu, lsum[1], 1);
    lsum[1] += __shfl_xor_sync(0xffffffffu, lsum[1], 2);
    const float inv0 = 1.0f / lsum[0];
    const float inv1 = 1.0f / lsum[1];

    const int b = bh >> 4;
    const int h = bh & (HH - 1);
    const int r0 = q0 + w * 16 + (lane >> 2);
    const int col = h * HDD + 2 * (lane & 3);
    __half* O0 = g_ctxh + ((size_t)b * SS + r0) * DD + col;
    __half* O1 = g_ctxh + ((size_t)b * SS + r0 + 8) * DD + col;
#pragma unroll
    for (int f = 0; f < 8; f++) {
        *reinterpret_cast<uint32_t*>(O0 + f * 8) = pack_h2(o[f][0] * inv0, o[f][1] * inv0);
        *reinterpret_cast<uint32_t*>(O1 + f * 8) = pack_h2(o[f][2] * inv1, o[f][3] * inv1);
    }
}

// ---------------------------------------------------------------------------
// Launch
// ---------------------------------------------------------------------------
extern "C" void kernel_launch(void* const* d_in, const int* in_sizes, int n_in,
                              void* d_out, int out_size) {
    const float* query = (const float*)d_in[0];
    const float* key_i = (const float*)d_in[1];
    const float* value = (const float*)d_in[2];
    const float* Wq = (const float*)d_in[3];
    const float* Wk = (const float*)d_in[4];
    const float* Wv = (const float*)d_in[5];
    const float* Wo = (const float*)d_in[6];
    const float* bo = (const float*)d_in[7];
    float* out = (float*)d_out;

    __half *qs, *ks, *vs, *ctxh, *w16;
    cudaGetSymbolAddress((void**)&qs, g_Qs);
    cudaGetSymbolAddress((void**)&ks, g_Ks);
    cudaGetSymbolAddress((void**)&vs, g_Vs);
    cudaGetSymbolAddress((void**)&ctxh, g_ctxh);
    cudaGetSymbolAddress((void**)&w16, g_W16);

    static bool attr_done = false;
    if (!attr_done) {
        cudaFuncSetAttribute(gemm_qkv, cudaFuncAttributeMaxDynamicSharedMemorySize, GEMM_SMEM);
        cudaFuncSetAttribute(gemm_out, cudaFuncAttributeMaxDynamicSharedMemorySize, GEMM_SMEM);
        attr_done = true;
    }

    // 1. all weights -> fp16
    conv_w<<<4 * (DD * DD / 4) / 256, 256>>>(Wq, Wk, Wv, Wo, w16);

    // 2. Q,K,V projections (fused A conversion), 128x256 tiles
    dim3 qgrid(DD / 256, MROWS / 128, 3);   // (4, 32, 3)
    gemm_qkv<<<qgrid, 512, GEMM_SMEM>>>(query, key_i, value, w16, qs, ks, vs);

    // 3. attention -> fp16 ctx
    dim3 agrid(SS / 128, BB * HH);
    attn_mma<<<agrid, 256>>>();

    // 4. output projection, 128x256 tiles
    dim3 ogrid(DD / 256, MROWS / 128);      // (4, 32)
    gemm_out<<<ogrid, 512, GEMM_SMEM>>>(ctxh, w16 + (size_t)3 * DD * DD, bo, out);
}

// round 15
// speedup vs baseline: 1.0559x; 1.0295x over previous
#include <cuda_runtime.h>
#include <cuda_fp16.h>
#include <cstdint>

// Problem constants
#define BB 2
#define SS 2048
#define DD 1024
#define HH 16
#define HDD 64
#define MROWS (BB * SS)          // 4096
static constexpr float QMULT = 1.4426950408889634f / 32.0f;  // log2(e)/sqrt(D)

// ---------------------------------------------------------------------------
// Device scratch
// ---------------------------------------------------------------------------
__device__ __half g_Qs[(size_t)BB * HH * SS * 64];   // [BH,S,64] (pre-scaled)
__device__ __half g_Ks[(size_t)BB * HH * SS * 64];
__device__ __half g_Vs[(size_t)BB * HH * SS * 64];
__device__ __half g_ctxh[(size_t)MROWS * DD];        // [B*S, D] fp16 ctx
__device__ __half g_W16[(size_t)4 * DD * DD];        // Wq|Wk|Wv|Wo fp16

// ---------------------------------------------------------------------------
// Helpers (baseline PTX only: cp.async / ldmatrix / mma.sync)
// ---------------------------------------------------------------------------
__device__ __forceinline__ uint32_t smem_u32(const void* p) {
    uint32_t a;
    asm("{ .reg .u64 t; cvta.to.shared.u64 t, %1; cvt.u32.u64 %0, t; }" : "=r"(a) : "l"(p));
    return a;
}
__device__ __forceinline__ void cp16(uint32_t s, const void* g) {
    asm volatile("cp.async.cg.shared.global [%0], [%1], 16;" :: "r"(s), "l"(g));
}
__device__ __forceinline__ void cp_commit() {
    asm volatile("cp.async.commit_group;" ::: "memory");
}
template <int N>
__device__ __forceinline__ void cp_wait() {
    asm volatile("cp.async.wait_group %0;" :: "n"(N) : "memory");
}
__device__ __forceinline__ void ldm_x4(uint32_t* r, uint32_t addr) {
    asm volatile("ldmatrix.sync.aligned.m8n8.x4.shared.b16 {%0,%1,%2,%3}, [%4];"
                 : "=r"(r[0]), "=r"(r[1]), "=r"(r[2]), "=r"(r[3]) : "r"(addr));
}
__device__ __forceinline__ void ldm_x4_t(uint32_t* r, uint32_t addr) {
    asm volatile("ldmatrix.sync.aligned.m8n8.x4.trans.shared.b16 {%0,%1,%2,%3}, [%4];"
                 : "=r"(r[0]), "=r"(r[1]), "=r"(r[2]), "=r"(r[3]) : "r"(addr));
}
__device__ __forceinline__ void mma16816(float* d, const uint32_t* a, const uint32_t* b) {
    asm volatile(
        "mma.sync.aligned.m16n8k16.row.col.f32.f16.f16.f32 "
        "{%0,%1,%2,%3}, {%4,%5,%6,%7}, {%8,%9}, {%0,%1,%2,%3};"
        : "+f"(d[0]), "+f"(d[1]), "+f"(d[2]), "+f"(d[3])
        : "r"(a[0]), "r"(a[1]), "r"(a[2]), "r"(a[3]), "r"(b[0]), "r"(b[1]));
}
__device__ __forceinline__ float ex2f(float x) {
    float r;
    asm("ex2.approx.ftz.f32 %0, %1;" : "=f"(r) : "f"(x));
    return r;
}
__device__ __forceinline__ uint32_t pack_h2(float x, float y) {
    __half2 h2; h2.x = __float2half_rn(x); h2.y = __float2half_rn(y);
    return *reinterpret_cast<uint32_t*>(&h2);
}

// ---------------------------------------------------------------------------
// Convert all 4 weight matrices fp32->fp16 in one launch.
// ---------------------------------------------------------------------------
__global__ __launch_bounds__(256) void conv_w(const float* __restrict__ w0,
                                              const float* __restrict__ w1,
                                              const float* __restrict__ w2,
                                              const float* __restrict__ w3,
                                              __half* __restrict__ out) {
    int idx = blockIdx.x * 256 + threadIdx.x;      // float4 units
    const int per = DD * DD / 4;                   // 262144
    int wsel = idx / per;
    int off = idx - wsel * per;
    const float* src = (wsel == 0) ? w0 : (wsel == 1) ? w1 : (wsel == 2) ? w2 : w3;
    float4 x = reinterpret_cast<const float4*>(src)[off];
    __half2 a; a.x = __float2half_rn(x.x); a.y = __float2half_rn(x.y);
    __half2 b; b.x = __float2half_rn(x.z); b.y = __float2half_rn(x.w);
    __half2* o = reinterpret_cast<__half2*>(out + (size_t)wsel * DD * DD) + off * 2;
    o[0] = a; o[1] = b;
}

// ---------------------------------------------------------------------------
// GEMM geometry: CTA tile 128(M) x 256(N), 512 threads = 16 warps (4m x 4n),
// warp tile 32x64. BK=64 chunks (16 total), 3-stage smem ring (144B rows),
// ONE barrier per 64-K chunk, loads issued after the barrier, loop unrolled.
// ---------------------------------------------------------------------------
#define GK 144                           // smem row stride in bytes
#define A_STG ((uint32_t)(128 * GK))     // 18432 B per A stage
#define B_STG ((uint32_t)(256 * GK))     // 36864 B per B stage
#define GEMM_SMEM (3 * (128 * GK) + 3 * (256 * GK))   // 165888 B
#define NK64 16                          // 64-K chunks

// ---------------------------------------------------------------------------
// QKV GEMM (fused A-side fp32->fp16): grid (4, 32, 3), 512 threads.
// ---------------------------------------------------------------------------
__global__ __launch_bounds__(512, 1) void gemm_qkv(const float* __restrict__ Aq,
                                                   const float* __restrict__ Ak,
                                                   const float* __restrict__ Av,
                                                   const __half* __restrict__ W16,
                                                   __half* __restrict__ qs,
                                                   __half* __restrict__ ks,
                                                   __half* __restrict__ vs) {
    extern __shared__ __align__(16) __half dsm[];
    const uint32_t base = smem_u32(dsm);
    auto sAa = [&](int st) { return base + (uint32_t)st * A_STG; };
    auto sBa = [&](int st) { return base + 3 * A_STG + (uint32_t)st * B_STG; };

    const int t = threadIdx.x;
    const int lane = t & 31;
    const int wid = t >> 5;            // 0..15
    const int wm = (wid >> 2) * 32;    // 0,32,64,96
    const int wn = (wid & 3) * 64;     // 0,64,128,192
    const int bm = blockIdx.y * 128;
    const int bn = blockIdx.x * 256;
    const int z = blockIdx.z;

    const float* A32 = (z == 0) ? Aq : (z == 1) ? Ak : Av;
    const __half* Bw = W16 + (size_t)z * DD * DD;
    __half* outp = (z == 0) ? qs : (z == 1) ? ks : vs;
    const float mult = (z == 0) ? QMULT : 1.0f;

    // A loader: 4 threads/row (128 rows); per half-chunk each thread does
    // 2 float4 LDG (8 fp32) -> one STS.v4 (8 fp16).
    const int arow = t >> 2;           // 0..127
    const int asg = t & 3;
    const float* Ag32 = A32 + (size_t)(bm + arow) * DD + asg * 8;
    const uint32_t asoff = (uint32_t)arow * GK + asg * 16;

    // B loader: 2 threads/row (256 rows), each 64B = 4 cp16
    const int brow = t >> 1;           // 0..255
    const int bsg = t & 1;
    const __half* Bg = Bw + (size_t)(bn + brow) * DD + bsg * 32;
    const uint32_t bsoff = (uint32_t)brow * GK + bsg * 64;

    float4 f0, f1;
    auto ldgA = [&](int kt, int h) {
        const float4* p = reinterpret_cast<const float4*>(Ag32 + kt * 64 + h * 32);
        f0 = p[0]; f1 = p[1];
    };
    auto stsA = [&](int st, int h) {
        uint32_t h0 = pack_h2(f0.x, f0.y), h1 = pack_h2(f0.z, f0.w);
        uint32_t h2 = pack_h2(f1.x, f1.y), h3 = pack_h2(f1.z, f1.w);
        asm volatile("st.shared.v4.b32 [%0], {%1,%2,%3,%4};"
                     :: "r"(sAa(st) + asoff + h * 64), "r"(h0), "r"(h1), "r"(h2), "r"(h3)
                     : "memory");
    };
    auto ldB = [&](int st, int kt) {
        const __half* p = Bg + kt * 64;
        cp16(sBa(st) + bsoff,      p);
        cp16(sBa(st) + bsoff + 16, p + 8);
        cp16(sBa(st) + bsoff + 32, p + 16);
        cp16(sBa(st) + bsoff + 48, p + 24);
        cp_commit();
    };

    const uint32_t aoff = (uint32_t)(wm + (lane & 15)) * GK + ((lane >> 4) << 4);
    const uint32_t boff = (uint32_t)(wn + (lane & 7) + ((lane >> 4) << 3)) * GK
                        + (((lane >> 3) & 1) << 4);

    float d[2][8][4];
#pragma unroll
    for (int i = 0; i < 2; i++)
#pragma unroll
        for (int j = 0; j < 8; j++)
#pragma unroll
            for (int r = 0; r < 4; r++) d[i][j][r] = 0.0f;

    // R12-style compute body over kf pair {kfb, kfb+1}
    auto comp = [&](int st, int kfb) {
        uint32_t a[2][2][4];
        uint32_t b[8][2][2];
#pragma unroll
        for (int mf = 0; mf < 2; mf++)
#pragma unroll
            for (int kk = 0; kk < 2; kk++)
                ldm_x4(a[mf][kk], sAa(st) + aoff + mf * 16 * GK + (kfb + kk) * 32);
#pragma unroll
        for (int ng = 0; ng < 4; ng++)
#pragma unroll
            for (int kk = 0; kk < 2; kk++) {
                uint32_t r[4];
                ldm_x4(r, sBa(st) + boff + ng * 16 * GK + (kfb + kk) * 32);
                b[2 * ng + 0][kk][0] = r[0]; b[2 * ng + 0][kk][1] = r[1];
                b[2 * ng + 1][kk][0] = r[2]; b[2 * ng + 1][kk][1] = r[3];
            }
#pragma unroll
        for (int mf = 0; mf < 2; mf++)
#pragma unroll
            for (int nf = 0; nf < 8; nf++) {
                mma16816(d[mf][nf], a[mf][0], b[nf][0]);
                mma16816(d[mf][nf], a[mf][1], b[nf][1]);
            }
    };

    // prologue: chunks 0,1 into stages 0,1
    ldgA(0, 0); stsA(0, 0); ldgA(0, 1); stsA(0, 1); ldB(0, 0);
    ldgA(1, 0); stsA(1, 0); ldgA(1, 1); stsA(1, 1); ldB(1, 1);

#pragma unroll
    for (int c = 0; c < NK64; ++c) {
        const int st = c % 3;
        const int sn = (c + 2) % 3;
        if (c + 2 < NK64) ldgA(c + 2, 0);          // early LDG (regs only)
        if (c + 2 < NK64) cp_wait<1>();
        else if (c + 1 < NK64) cp_wait<1>();
        else cp_wait<0>();
        __syncthreads();
        if (c + 2 < NK64) {                        // stage sn free: read ended @ iter c-1
            ldB(sn, c + 2);
            stsA(sn, 0);
            ldgA(c + 2, 1);
        }
        comp(st, 0);
        comp(st, 2);
        if (c + 2 < NK64) stsA(sn, 1);
    }

    // Epilogue: warp owns one head (wn = 64 consecutive n)
    const int hh = (bn + wn) >> 6;
    const int hd0 = 2 * (lane & 3);
    const int mrow = bm + wm + (lane >> 2);
#pragma unroll
    for (int mf = 0; mf < 2; mf++) {
#pragma unroll
        for (int half = 0; half < 2; half++) {
            const int m = mrow + mf * 16 + half * 8;
            const int b = m >> 11;
            const int s = m & (SS - 1);
            __half* bp = outp + (((size_t)b * HH + hh) * SS + s) * 64 + hd0;
#pragma unroll
            for (int nf = 0; nf < 8; nf++) {
                *reinterpret_cast<uint32_t*>(bp + nf * 8) =
                    pack_h2(d[mf][nf][half * 2 + 0] * mult,
                            d[mf][nf][half * 2 + 1] * mult);
            }
        }
    }
}

// ---------------------------------------------------------------------------
// Output GEMM: A = fp16 ctx, B = Wo fp16 (both cp.async), bias, fp32 out.
// grid (4, 32), 512 threads, BK=64, 3-stage ring.
// ---------------------------------------------------------------------------
__global__ __launch_bounds__(512, 1) void gemm_out(const __half* __restrict__ A16,
                                                   const __half* __restrict__ W16,
                                                   const float* __restrict__ bias,
                                                   float* __restrict__ out) {
    extern __shared__ __align__(16) __half dsm[];
    const uint32_t base = smem_u32(dsm);
    auto sAa = [&](int st) { return base + (uint32_t)st * A_STG; };
    auto sBa = [&](int st) { return base + 3 * A_STG + (uint32_t)st * B_STG; };

    const int t = threadIdx.x;
    const int lane = t & 31;
    const int wid = t >> 5;
    const int wm = (wid >> 2) * 32;
    const int wn = (wid & 3) * 64;
    const int bm = blockIdx.y * 128;
    const int bn = blockIdx.x * 256;

    // A loader: 4 threads/row, 32B each = 2 cp16
    const int arow = t >> 2;
    const int asg = t & 3;
    const __half* Ag = A16 + (size_t)(bm + arow) * DD + asg * 16;
    const uint32_t asoff = (uint32_t)arow * GK + asg * 32;
    // B loader: 2 threads/row, 64B each = 4 cp16
    const int brow = t >> 1;
    const int bsg = t & 1;
    const __half* Bg = W16 + (size_t)(bn + brow) * DD + bsg * 32;
    const uint32_t bsoff = (uint32_t)brow * GK + bsg * 64;

    auto load_tile = [&](int st, int kt) {
        const __half* pa = Ag + kt * 64;
        const __half* pb = Bg + kt * 64;
        cp16(sAa(st) + asoff,      pa);
        cp16(sAa(st) + asoff + 16, pa + 8);
        cp16(sBa(st) + bsoff,      pb);
        cp16(sBa(st) + bsoff + 16, pb + 8);
        cp16(sBa(st) + bsoff + 32, pb + 16);
        cp16(sBa(st) + bsoff + 48, pb + 24);
        cp_commit();
    };

    const uint32_t aoff = (uint32_t)(wm + (lane & 15)) * GK + ((lane >> 4) << 4);
    const uint32_t boff = (uint32_t)(wn + (lane & 7) + ((lane >> 4) << 3)) * GK
                        + (((lane >> 3) & 1) << 4);

    float d[2][8][4];
#pragma unroll
    for (int i = 0; i < 2; i++)
#pragma unroll
        for (int j = 0; j < 8; j++)
#pragma unroll
            for (int r = 0; r < 4; r++) d[i][j][r] = 0.0f;

    auto comp = [&](int st, int kfb) {
        uint32_t a[2][2][4];
        uint32_t b[8][2][2];
#pragma unroll
        for (int mf = 0; mf < 2; mf++)
#pragma unroll
            for (int kk = 0; kk < 2; kk++)
                ldm_x4(a[mf][kk], sAa(st) + aoff + mf * 16 * GK + (kfb + kk) * 32);
#pragma unroll
        for (int ng = 0; ng < 4; ng++)
#pragma unroll
            for (int kk = 0; kk < 2; kk++) {
                uint32_t r[4];
                ldm_x4(r, sBa(st) + boff + ng * 16 * GK + (kfb + kk) * 32);
                b[2 * ng + 0][kk][0] = r[0]; b[2 * ng + 0][kk][1] = r[1];
                b[2 * ng + 1][kk][0] = r[2]; b[2 * ng + 1][kk][1] = r[3];
            }
#pragma unroll
        for (int mf = 0; mf < 2; mf++)
#pragma unroll
            for (int nf = 0; nf < 8; nf++) {
                mma16816(d[mf][nf], a[mf][0], b[nf][0]);
                mma16816(d[mf][nf], a[mf][1], b[nf][1]);
            }
    };

    load_tile(0, 0);
    load_tile(1, 1);

#pragma unroll
    for (int c = 0; c < NK64; ++c) {
        const int st = c % 3;
        const int sn = (c + 2) % 3;
        if (c + 2 < NK64) cp_wait<1>();
        else if (c + 1 < NK64) cp_wait<1>();
        else cp_wait<0>();
        __syncthreads();
        if (c + 2 < NK64) load_tile(sn, c + 2);
        comp(st, 0);
        comp(st, 2);
    }

    const int mrow = bm + wm + (lane >> 2);
    const int ncol0 = bn + wn + 2 * (lane & 3);
#pragma unroll
    for (int mf = 0; mf < 2; mf++) {
#pragma unroll
        for (int half = 0; half < 2; half++) {
            const int m = mrow + mf * 16 + half * 8;
            float* orow = out + (size_t)m * DD;
#pragma unroll
            for (int nf = 0; nf < 8; nf++) {
                const int n = ncol0 + nf * 8;
                float2 o;
                o.x = d[mf][nf][half * 2 + 0] + bias[n];
                o.y = d[mf][nf][half * 2 + 1] + bias[n + 1];
                *reinterpret_cast<float2*>(orow + n) = o;
            }
        }
    }
}

// ---------------------------------------------------------------------------
// Tensor-core flash attention: pair-granularity buffering (4 tile-buffers),
// ONE barrier per 2 tiles, 1-ahead ldmatrix prefetch. 2 CTAs/SM.
// grid (S/128, B*H), 256 threads (8 warps x 16 q rows). Dynamic smem 72KB.
// ---------------------------------------------------------------------------
#define LDK 72    // K/V/Q smem row stride in halfwords (144B)
#define TILE_B ((uint32_t)(64 * LDK * 2))          // 9216 B per K or V tile
#define ATTN_SMEM (4 * 2 * 64 * LDK * 2)           // 73728 B

__global__ __launch_bounds__(256, 2) void attn_mma() {
    extern __shared__ __align__(16) __half asm_[];
    const uint32_t sbase = smem_u32(asm_);
    auto bufK = [&](int i) { return sbase + (uint32_t)i * (2 * TILE_B); };
    auto bufV = [&](int i) { return sbase + (uint32_t)i * (2 * TILE_B) + TILE_B; };

    const int t = threadIdx.x;
    const int lane = t & 31;
    const int w = t >> 5;
    const int bh = blockIdx.y;
    const int q0 = blockIdx.x * 128;

    // ---- stage Q tile (128 rows x 128B), grab A-fragments ----
    const __half* Qg = g_Qs + ((size_t)bh * SS + q0) * 64;
#pragma unroll
    for (int i = 0; i < 4; i++) {
        int idx = i * 256 + t;
        int row = idx >> 3, ch = idx & 7;
        cp16(sbase + row * (LDK * 2) + ch * 16, Qg + (size_t)row * 64 + ch * 8);
    }
    cp_commit(); cp_wait<0>();
    __syncthreads();

    uint32_t qa[4][4];
    const uint32_t aoff = (uint32_t)(w * 16 + (lane & 15)) * (LDK * 2) + ((lane >> 4) << 4);
#pragma unroll
    for (int kf = 0; kf < 4; kf++) ldm_x4(qa[kf], sbase + aoff + kf * 32);
    __syncthreads();

    float o[8][4];
#pragma unroll
    for (int f = 0; f < 8; f++)
#pragma unroll
        for (int r = 0; r < 4; r++) o[f][r] = 0.0f;
    float mrow[2] = { -1e30f, -1e30f };
    float lsum[2] = { 0.0f, 0.0f };

    const __half* Kg = g_Ks + (size_t)bh * SS * 64;
    const __half* Vg = g_Vs + (size_t)bh * SS * 64;

    const uint32_t boff = (uint32_t)((lane & 7) + ((lane >> 4) << 3)) * (LDK * 2)
                        + (((lane >> 3) & 1) << 4);
    const uint32_t voff = (uint32_t)(lane & 15) * (LDK * 2) + ((lane >> 4) << 4);

    auto issueTile = [&](int bi, int it) {
        const int k0 = it * 64;
#pragma unroll
        for (int i = 0; i < 2; i++) {
            int idx = i * 256 + t;
            int row = idx >> 3, ch = idx & 7;
            cp16(bufK(bi) + row * (LDK * 2) + ch * 16, Kg + ((size_t)(k0 + row)) * 64 + ch * 8);
            cp16(bufV(bi) + row * (LDK * 2) + ch * 16, Vg + ((size_t)(k0 + row)) * 64 + ch * 8);
        }
    };

    auto tile_body = [&](int bi) {
        const uint32_t sK = bufK(bi);
        const uint32_t sV = bufV(bi);
        // ---- S = Q K^T with 1-ahead K-fragment prefetch ----
        float s[8][4];
#pragma unroll
        for (int f = 0; f < 8; f++)
#pragma unroll
            for (int r = 0; r < 4; r++) s[f][r] = 0.0f;
        {
            uint32_t bk[2][4];
            ldm_x4(bk[0], sK + boff);
#pragma unroll
            for (int idx = 0; idx < 16; idx++) {
                const int kf = idx >> 2, nc = idx & 3;
                if (idx < 15) {
                    const int kf2 = (idx + 1) >> 2, nc2 = (idx + 1) & 3;
                    ldm_x4(bk[(idx + 1) & 1],
                           sK + boff + nc2 * 16 * (LDK * 2) + kf2 * 32);
                }
                mma16816(s[2 * nc],     qa[kf], bk[idx & 1] + 0);
                mma16816(s[2 * nc + 1], qa[kf], bk[idx & 1] + 2);
            }
        }

        // ---- online softmax ----
        float tm0 = -1e30f, tm1 = -1e30f;
#pragma unroll
        for (int f = 0; f < 8; f++) {
            tm0 = fmaxf(tm0, fmaxf(s[f][0], s[f][1]));
            tm1 = fmaxf(tm1, fmaxf(s[f][2], s[f][3]));
        }
        tm0 = fmaxf(tm0, __shfl_xor_sync(0xffffffffu, tm0, 1));
        tm0 = fmaxf(tm0, __shfl_xor_sync(0xffffffffu, tm0, 2));
        tm1 = fmaxf(tm1, __shfl_xor_sync(0xffffffffu, tm1, 1));
        tm1 = fmaxf(tm1, __shfl_xor_sync(0xffffffffu, tm1, 2));
        const float mn0 = fmaxf(mrow[0], tm0);
        const float mn1 = fmaxf(mrow[1], tm1);
        const float sc0 = ex2f(mrow[0] - mn0);
        const float sc1 = ex2f(mrow[1] - mn1);
        mrow[0] = mn0; mrow[1] = mn1;
        lsum[0] *= sc0; lsum[1] *= sc1;
#pragma unroll
        for (int f = 0; f < 8; f++) {
            o[f][0] *= sc0; o[f][1] *= sc0;
            o[f][2] *= sc1; o[f][3] *= sc1;
        }

        // ---- P = exp2(S - m), pack into A-fragments ----
        uint32_t ph[4][4];
#pragma unroll
        for (int kf = 0; kf < 4; kf++) {
#pragma unroll
            for (int j = 0; j < 2; j++) {
                float* sf = s[2 * kf + j];
                float p0 = ex2f(sf[0] - mn0);
                float p1 = ex2f(sf[1] - mn0);
                float p2 = ex2f(sf[2] - mn1);
                float p3 = ex2f(sf[3] - mn1);
                lsum[0] += p0 + p1;
                lsum[1] += p2 + p3;
                ph[kf][2 * j + 0] = pack_h2(p0, p1);
                ph[kf][2 * j + 1] = pack_h2(p2, p3);
            }
        }

        // ---- O += P V with 1-ahead V-fragment prefetch ----
        {
            uint32_t bv[2][4];
            ldm_x4_t(bv[0], sV + voff);
#pragma unroll
            for (int idx = 0; idx < 16; idx++) {
                const int kf = idx >> 2, nc = idx & 3;
                if (idx < 15) {
                    const int kf2 = (idx + 1) >> 2, nc2 = (idx + 1) & 3;
                    ldm_x4_t(bv[(idx + 1) & 1],
                             sV + voff + kf2 * 16 * (LDK * 2) + nc2 * 32);
                }
                mma16816(o[2 * nc],     ph[kf], bv[idx & 1] + 0);
                mma16816(o[2 * nc + 1], ph[kf], bv[idx & 1] + 2);
            }
        }
    };

    constexpr int NP = SS / 128;   // 16 pairs
    // prologue: pair 0 (tiles 0,1 -> buffers 0,1)
    issueTile(0, 0); issueTile(1, 1); cp_commit();

    for (int p = 0; p < NP; ++p) {
        cp_wait<0>();
        __syncthreads();
        if (p + 1 < NP) {   // pair p+1 -> buffers (2p+2)&3, (2p+3)&3
            issueTile((2 * p + 2) & 3, 2 * p + 2);
            issueTile((2 * p + 3) & 3, 2 * p + 3);
            cp_commit();
        }
        tile_body((2 * p) & 3);
        tile_body((2 * p + 1) & 3);
    }

    lsum[0] += __shfl_xor_sync(0xffffffffu, lsum[0], 1);
    lsum[0] += __shfl_xor_sync(0xffffffffu, lsum[0], 2);
    lsum[1] += __shfl_xor_sync(0xffffffffu, lsum[1], 1);
    lsum[1] += __shfl_xor_sync(0xffffffffu, lsum[1], 2);
    const float inv0 = 1.0f / lsum[0];
    const float inv1 = 1.0f / lsum[1];

    const int b = bh >> 4;
    const int h = bh & (HH - 1);
    const int r0 = q0 + w * 16 + (lane >> 2);
    const int col = h * HDD + 2 * (lane & 3);
    __half* O0 = g_ctxh + ((size_t)b * SS + r0) * DD + col;
    __half* O1 = g_ctxh + ((size_t)b * SS + r0 + 8) * DD + col;
#pragma unroll
    for (int f = 0; f < 8; f++) {
        *reinterpret_cast<uint32_t*>(O0 + f * 8) = pack_h2(o[f][0] * inv0, o[f][1] * inv0);
        *reinterpret_cast<uint32_t*>(O1 + f * 8) = pack_h2(o[f][2] * inv1, o[f][3] * inv1);
    }
}

// ---------------------------------------------------------------------------
// Launch
// ---------------------------------------------------------------------------
extern "C" void kernel_launch(void* const* d_in, const int* in_sizes, int n_in,
                              void* d_out, int out_size) {
    const float* query = (const float*)d_in[0];
    const float* key_i = (const float*)d_in[1];
    const float* value = (const float*)d_in[2];
    const float* Wq = (const float*)d_in[3];
    const float* Wk = (const float*)d_in[4];
    const float* Wv = (const float*)d_in[5];
    const float* Wo = (const float*)d_in[6];
    const float* bo = (const float*)d_in[7];
    float* out = (float*)d_out;

    __half *qs, *ks, *vs, *ctxh, *w16;
    cudaGetSymbolAddress((void**)&qs, g_Qs);
    cudaGetSymbolAddress((void**)&ks, g_Ks);
    cudaGetSymbolAddress((void**)&vs, g_Vs);
    cudaGetSymbolAddress((void**)&ctxh, g_ctxh);
    cudaGetSymbolAddress((void**)&w16, g_W16);

    static bool attr_done = false;
    if (!attr_done) {
        cudaFuncSetAttribute(gemm_qkv, cudaFuncAttributeMaxDynamicSharedMemorySize, GEMM_SMEM);
        cudaFuncSetAttribute(gemm_out, cudaFuncAttributeMaxDynamicSharedMemorySize, GEMM_SMEM);
        cudaFuncSetAttribute(attn_mma, cudaFuncAttributeMaxDynamicSharedMemorySize, ATTN_SMEM);
        attr_done = true;
    }

    // 1. all weights -> fp16
    conv_w<<<4 * (DD * DD / 4) / 256, 256>>>(Wq, Wk, Wv, Wo, w16);

    // 2. Q,K,V projections (fused A conversion), 128x256 tiles
    dim3 qgrid(DD / 256, MROWS / 128, 3);   // (4, 32, 3)
    gemm_qkv<<<qgrid, 512, GEMM_SMEM>>>(query, key_i, value, w16, qs, ks, vs);

    // 3. attention -> fp16 ctx
    dim3 agrid(SS / 128, BB * HH);
    attn_mma<<<agrid, 256, ATTN_SMEM>>>();

    // 4. output projection, 128x256 tiles
    dim3 ogrid(DD / 256, MROWS / 128);      // (4, 32)
    gemm_out<<<ogrid, 512, GEMM_SMEM>>>(ctxh, w16 + (size_t)3 * DD * DD, bo, out);
}